// round 2
// baseline (speedup 1.0000x reference)
#include <cuda_runtime.h>
#include <math.h>

#define Bn   2
#define Ln   1024
#define Dn   1024
#define Hn   16
#define HDn  64
#define HIDn 4096
#define Mn   (Bn*Ln)        /* 2048 rows */
#define EPSc 1e-6f
#define SCALEc 0.125f       /* 64^-0.5 */

// ---------------- scratch (device globals; no runtime allocation) ----------
__device__ float g_hr[Mn*Dn],  g_hi[Mn*Dn];
__device__ float g_qr[Mn*Dn],  g_qi[Mn*Dn];
__device__ float g_kr[Mn*Dn],  g_ki[Mn*Dn];
__device__ float g_vr[Mn*Dn],  g_vi[Mn*Dn];
__device__ float g_s [Bn*Hn*Ln*Ln];          /* 128 MB scores/attn */
__device__ float g_aor[Mn*Dn], g_aoi[Mn*Dn];
__device__ float g_ar[Mn*Dn],  g_ai[Mn*Dn];
__device__ float g_fr[Mn*HIDn], g_fi[Mn*HIDn];

// ---------------- complex layernorm ----------------------------------------
__global__ void cln_kernel(const float* __restrict__ xr, const float* __restrict__ xi,
                           const float* __restrict__ gr, const float* __restrict__ gi,
                           const float* __restrict__ bre, const float* __restrict__ bim,
                           float* __restrict__ outr, float* __restrict__ outi)
{
    int row = blockIdx.x;
    const float* pr = xr + (size_t)row * Dn;
    const float* pi = xi + (size_t)row * Dn;
    __shared__ float s1[256], s2[256];
    int tid = threadIdx.x;
    float sr = 0.f, si = 0.f;
    for (int j = tid; j < Dn; j += 256) { sr += pr[j]; si += pi[j]; }
    s1[tid] = sr; s2[tid] = si;
    __syncthreads();
    for (int o = 128; o > 0; o >>= 1) {
        if (tid < o) { s1[tid] += s1[tid+o]; s2[tid] += s2[tid+o]; }
        __syncthreads();
    }
    float mr = s1[0] * (1.f/Dn), mi = s2[0] * (1.f/Dn);
    __syncthreads();
    float v = 0.f;
    for (int j = tid; j < Dn; j += 256) {
        float cr = pr[j] - mr, ci = pi[j] - mi;
        v += cr*cr + ci*ci;
    }
    s1[tid] = v;
    __syncthreads();
    for (int o = 128; o > 0; o >>= 1) {
        if (tid < o) s1[tid] += s1[tid+o];
        __syncthreads();
    }
    float inv = rsqrtf(s1[0] * (1.f/Dn) + EPSc);
    for (int j = tid; j < Dn; j += 256) {
        float nr = (pr[j]-mr)*inv, ni = (pi[j]-mi)*inv;
        outr[(size_t)row*Dn + j] = nr*gr[j] - ni*gi[j] + bre[j];
        outi[(size_t)row*Dn + j] = nr*gi[j] + ni*gr[j] + bim[j];
    }
}

// ---------------- complex GEMM: C = A @ B^T (A:[M,K], B:[N,K] row-major) ----
// optional bias[N] and residual[M,N] in epilogue
__global__ __launch_bounds__(256, 2)
void cgemm_nt(const float* __restrict__ Ar, const float* __restrict__ Ai,
              const float* __restrict__ Br, const float* __restrict__ Bi,
              float* __restrict__ Cr, float* __restrict__ Ci,
              int M, int N, int K,
              const float* __restrict__ biasr, const float* __restrict__ biasi,
              const float* __restrict__ resr,  const float* __restrict__ resi)
{
    __shared__ float Asr[16][132], Asi[16][132];
    __shared__ float Bsr[16][68],  Bsi[16][68];
    const int tid = threadIdx.x;
    const int bm = blockIdx.y * 128, bn = blockIdx.x * 64;
    const int tx = tid & 15, ty = tid >> 4;
    const int r0 = ty * 8, c0 = tx * 4;
    const int lm = tid >> 2, lk = (tid & 3) * 4;

    float cr[8][4], ci[8][4];
#pragma unroll
    for (int i = 0; i < 8; i++)
#pragma unroll
        for (int j = 0; j < 4; j++) { cr[i][j] = 0.f; ci[i][j] = 0.f; }

    for (int k0 = 0; k0 < K; k0 += 16) {
#pragma unroll
        for (int p = 0; p < 2; p++) {
            int row = bm + p*64 + lm;
            float4 a4r = *(const float4*)(Ar + (size_t)row * K + k0 + lk);
            float4 a4i = *(const float4*)(Ai + (size_t)row * K + k0 + lk);
            int col = p*64 + lm;
            Asr[lk+0][col] = a4r.x; Asr[lk+1][col] = a4r.y;
            Asr[lk+2][col] = a4r.z; Asr[lk+3][col] = a4r.w;
            Asi[lk+0][col] = a4i.x; Asi[lk+1][col] = a4i.y;
            Asi[lk+2][col] = a4i.z; Asi[lk+3][col] = a4i.w;
        }
        {
            int row = bn + lm;
            float4 b4r = *(const float4*)(Br + (size_t)row * K + k0 + lk);
            float4 b4i = *(const float4*)(Bi + (size_t)row * K + k0 + lk);
            Bsr[lk+0][lm] = b4r.x; Bsr[lk+1][lm] = b4r.y;
            Bsr[lk+2][lm] = b4r.z; Bsr[lk+3][lm] = b4r.w;
            Bsi[lk+0][lm] = b4i.x; Bsi[lk+1][lm] = b4i.y;
            Bsi[lk+2][lm] = b4i.z; Bsi[lk+3][lm] = b4i.w;
        }
        __syncthreads();
#pragma unroll
        for (int kk = 0; kk < 16; kk++) {
            float ar[8], ai[8], br[4], bi[4];
            *(float4*)&ar[0] = *(const float4*)&Asr[kk][r0];
            *(float4*)&ar[4] = *(const float4*)&Asr[kk][r0+4];
            *(float4*)&ai[0] = *(const float4*)&Asi[kk][r0];
            *(float4*)&ai[4] = *(const float4*)&Asi[kk][r0+4];
            *(float4*)&br[0] = *(const float4*)&Bsr[kk][c0];
            *(float4*)&bi[0] = *(const float4*)&Bsi[kk][c0];
#pragma unroll
            for (int i = 0; i < 8; i++)
#pragma unroll
                for (int j = 0; j < 4; j++) {
                    cr[i][j] = fmaf(ar[i],  br[j], cr[i][j]);
                    cr[i][j] = fmaf(-ai[i], bi[j], cr[i][j]);
                    ci[i][j] = fmaf(ar[i],  bi[j], ci[i][j]);
                    ci[i][j] = fmaf(ai[i],  br[j], ci[i][j]);
                }
        }
        __syncthreads();
    }
#pragma unroll
    for (int i = 0; i < 8; i++) {
        int row = bm + r0 + i;
#pragma unroll
        for (int j = 0; j < 4; j++) {
            int col = bn + c0 + j;
            float vr = cr[i][j], vi = ci[i][j];
            if (biasr) { vr += biasr[col]; vi += biasi[col]; }
            if (resr)  { vr += resr[(size_t)row*N + col]; vi += resi[(size_t)row*N + col]; }
            Cr[(size_t)row*N + col] = vr;
            Ci[(size_t)row*N + col] = vi;
        }
    }
}

// ---------------- RoPE (in place, per (b,l,h, pair j<32)) ------------------
__global__ void rope_kernel(float* __restrict__ xr, float* __restrict__ xi)
{
    int idx = blockIdx.x * blockDim.x + threadIdx.x;   // Bn*Ln*Hn*32 threads
    int j = idx & 31;
    int t = idx >> 5;
    int h = t & (Hn-1); t >>= 4;
    int l = t & (Ln-1);
    int b = t >> 10;
    size_t base = ((size_t)(b*Ln + l)) * Dn + h * HDn;
    double invf = exp(-((double)(2*j) / (double)HDn) * 9.210340371976184); // ln(1e4)
    double th = (double)l * invf;
    double sd, cd;
    sincos(th, &sd, &cd);
    float c = (float)cd, s = (float)sd;
    float a0 = xr[base+j], a1 = xr[base+j+32];
    xr[base+j]    = a0*c - a1*s;
    xr[base+j+32] = a1*c + a0*s;
    float b0 = xi[base+j], b1 = xi[base+j+32];
    xi[base+j]    = b0*c - b1*s;
    xi[base+j+32] = b1*c + b0*s;
}

// ---------------- scores = (Qr Kr^T + Qi Ki^T) * SCALE, causal-block-skip ---
__global__ __launch_bounds__(256, 2)
void scores_kernel(const float* __restrict__ Q_r, const float* __restrict__ Q_i,
                   const float* __restrict__ K_r, const float* __restrict__ K_i,
                   float* __restrict__ S)
{
    int bh = blockIdx.z;
    int b = bh >> 4, h = bh & 15;
    int bm = blockIdx.y * 128, bn = blockIdx.x * 64;
    if (bn > bm + 127) return;                      // fully masked block
    const size_t off = (size_t)b * Ln * Dn + (size_t)h * HDn;
    const float* Ar = Q_r + off; const float* Ai = Q_i + off;
    const float* Br = K_r + off; const float* Bi = K_i + off;
    __shared__ float Asr[16][132], Asi[16][132], Bsr[16][68], Bsi[16][68];
    const int tid = threadIdx.x;
    const int tx = tid & 15, ty = tid >> 4;
    const int r0 = ty * 8, c0 = tx * 4;
    const int lm = tid >> 2, lk = (tid & 3) * 4;
    float acc[8][4];
#pragma unroll
    for (int i = 0; i < 8; i++)
#pragma unroll
        for (int j = 0; j < 4; j++) acc[i][j] = 0.f;

#pragma unroll
    for (int k0 = 0; k0 < HDn; k0 += 16) {
#pragma unroll
        for (int p = 0; p < 2; p++) {
            int row = bm + p*64 + lm;
            float4 a4r = *(const float4*)(Ar + (size_t)row * Dn + k0 + lk);
            float4 a4i = *(const float4*)(Ai + (size_t)row * Dn + k0 + lk);
            int col = p*64 + lm;
            Asr[lk+0][col] = a4r.x; Asr[lk+1][col] = a4r.y;
            Asr[lk+2][col] = a4r.z; Asr[lk+3][col] = a4r.w;
            Asi[lk+0][col] = a4i.x; Asi[lk+1][col] = a4i.y;
            Asi[lk+2][col] = a4i.z; Asi[lk+3][col] = a4i.w;
        }
        {
            int row = bn + lm;
            float4 b4r = *(const float4*)(Br + (size_t)row * Dn + k0 + lk);
            float4 b4i = *(const float4*)(Bi + (size_t)row * Dn + k0 + lk);
            Bsr[lk+0][lm] = b4r.x; Bsr[lk+1][lm] = b4r.y;
            Bsr[lk+2][lm] = b4r.z; Bsr[lk+3][lm] = b4r.w;
            Bsi[lk+0][lm] = b4i.x; Bsi[lk+1][lm] = b4i.y;
            Bsi[lk+2][lm] = b4i.z; Bsi[lk+3][lm] = b4i.w;
        }
        __syncthreads();
#pragma unroll
        for (int kk = 0; kk < 16; kk++) {
            float ar[8], ai[8], br[4], bi[4];
            *(float4*)&ar[0] = *(const float4*)&Asr[kk][r0];
            *(float4*)&ar[4] = *(const float4*)&Asr[kk][r0+4];
            *(float4*)&ai[0] = *(const float4*)&Asi[kk][r0];
            *(float4*)&ai[4] = *(const float4*)&Asi[kk][r0+4];
            *(float4*)&br[0] = *(const float4*)&Bsr[kk][c0];
            *(float4*)&bi[0] = *(const float4*)&Bsi[kk][c0];
#pragma unroll
            for (int i = 0; i < 8; i++)
#pragma unroll
                for (int j = 0; j < 4; j++) {
                    acc[i][j] = fmaf(ar[i], br[j], acc[i][j]);
                    acc[i][j] = fmaf(ai[i], bi[j], acc[i][j]);
                }
        }
        __syncthreads();
    }
#pragma unroll
    for (int i = 0; i < 8; i++) {
        int row = bm + r0 + i;
#pragma unroll
        for (int j = 0; j < 4; j++) {
            int col = bn + c0 + j;
            S[((size_t)bh * Ln + row) * Ln + col] = acc[i][j] * SCALEc;
        }
    }
}

// ---------------- causal softmax (in place), zeros above diagonal -----------
__global__ void softmax_kernel(float* __restrict__ S)
{
    int row = blockIdx.x;                 // 0 .. B*H*L-1
    int l = row & (Ln - 1);
    float* p = S + (size_t)row * Ln;
    __shared__ float red[256];
    int tid = threadIdx.x;
    float m = -1e30f;
    for (int j = tid; j <= l; j += 256) m = fmaxf(m, p[j]);
    red[tid] = m; __syncthreads();
    for (int o = 128; o > 0; o >>= 1) {
        if (tid < o) red[tid] = fmaxf(red[tid], red[tid+o]);
        __syncthreads();
    }
    m = red[0]; __syncthreads();
    float s = 0.f;
    for (int j = tid; j <= l; j += 256) s += expf(p[j] - m);
    red[tid] = s; __syncthreads();
    for (int o = 128; o > 0; o >>= 1) {
        if (tid < o) red[tid] += red[tid+o];
        __syncthreads();
    }
    float inv = 1.f / red[0];
    for (int j = tid; j < Ln; j += 256)
        p[j] = (j <= l) ? expf(p[j] - m) * inv : 0.f;
}

// ---------------- out = attn @ V (both r and i), causal k-loop truncation ---
__global__ __launch_bounds__(256, 2)
void av_kernel(const float* __restrict__ S,
               const float* __restrict__ V_r, const float* __restrict__ V_i,
               float* __restrict__ Or, float* __restrict__ Oi)
{
    int bh = blockIdx.z;
    int b = bh >> 4, h = bh & 15;
    int bm = blockIdx.y * 128;
    const float* P = S + (size_t)bh * Ln * Ln;
    const size_t voff = (size_t)b * Ln * Dn + (size_t)h * HDn;
    __shared__ float As[16][132], Bsr[16][68], Bsi[16][68];
    const int tid = threadIdx.x;
    const int tx = tid & 15, ty = tid >> 4;
    const int r0 = ty * 8, c0 = tx * 4;
    const int lm = tid >> 2, lk = (tid & 3) * 4;
    const int vrow = tid >> 4, vc4 = (tid & 15) * 4;
    float cr[8][4], ci[8][4];
#pragma unroll
    for (int i = 0; i < 8; i++)
#pragma unroll
        for (int j = 0; j < 4; j++) { cr[i][j] = 0.f; ci[i][j] = 0.f; }

    int kmax = bm + 128;                   // rows in this block see m <= bm+127
    for (int k0 = 0; k0 < kmax; k0 += 16) {
#pragma unroll
        for (int p = 0; p < 2; p++) {
            int row = bm + p*64 + lm;
            float4 a4 = *(const float4*)(P + (size_t)row * Ln + k0 + lk);
            int col = p*64 + lm;
            As[lk+0][col] = a4.x; As[lk+1][col] = a4.y;
            As[lk+2][col] = a4.z; As[lk+3][col] = a4.w;
        }
        {
            float4 v4r = *(const float4*)(V_r + voff + (size_t)(k0 + vrow) * Dn + vc4);
            float4 v4i = *(const float4*)(V_i + voff + (size_t)(k0 + vrow) * Dn + vc4);
            Bsr[vrow][vc4+0] = v4r.x; Bsr[vrow][vc4+1] = v4r.y;
            Bsr[vrow][vc4+2] = v4r.z; Bsr[vrow][vc4+3] = v4r.w;
            Bsi[vrow][vc4+0] = v4i.x; Bsi[vrow][vc4+1] = v4i.y;
            Bsi[vrow][vc4+2] = v4i.z; Bsi[vrow][vc4+3] = v4i.w;
        }
        __syncthreads();
#pragma unroll
        for (int kk = 0; kk < 16; kk++) {
            float a[8], br[4], bi[4];
            *(float4*)&a[0] = *(const float4*)&As[kk][r0];
            *(float4*)&a[4] = *(const float4*)&As[kk][r0+4];
            *(float4*)&br[0] = *(const float4*)&Bsr[kk][c0];
            *(float4*)&bi[0] = *(const float4*)&Bsi[kk][c0];
#pragma unroll
            for (int i = 0; i < 8; i++)
#pragma unroll
                for (int j = 0; j < 4; j++) {
                    cr[i][j] = fmaf(a[i], br[j], cr[i][j]);
                    ci[i][j] = fmaf(a[i], bi[j], ci[i][j]);
                }
        }
        __syncthreads();
    }
#pragma unroll
    for (int i = 0; i < 8; i++) {
        int row = bm + r0 + i;
#pragma unroll
        for (int j = 0; j < 4; j++) {
            Or[voff + (size_t)row * Dn + c0 + j] = cr[i][j];
            Oi[voff + (size_t)row * Dn + c0 + j] = ci[i][j];
        }
    }
}

// ---------------- ModReLU ---------------------------------------------------
__global__ void modrelu_kernel(float* __restrict__ fr, float* __restrict__ fi,
                               const float* __restrict__ mb)
{
    size_t idx = (size_t)blockIdx.x * blockDim.x + threadIdx.x;
    int col = (int)(idx & (HIDn - 1));
    float r = fr[idx], i = fi[idx];
    float mag = sqrtf(r*r + i*i);
    float safe = mag > 0.f ? mag : 1.f;
    float act = fmaxf(mag + mb[col], 0.f);
    float fac = act / safe;
    fr[idx] = r * fac;
    fi[idx] = i * fac;
}

// ---------------- launch ----------------------------------------------------
extern "C" void kernel_launch(void* const* d_in, const int* in_sizes, int n_in,
                              void* d_out, int out_size)
{
    const float* x_r   = (const float*)d_in[0];
    const float* x_i   = (const float*)d_in[1];
    const float* Wq_r  = (const float*)d_in[2];
    const float* Wq_i  = (const float*)d_in[3];
    const float* Wk_r  = (const float*)d_in[4];
    const float* Wk_i  = (const float*)d_in[5];
    const float* Wv_r  = (const float*)d_in[6];
    const float* Wv_i  = (const float*)d_in[7];
    const float* Wo_r  = (const float*)d_in[8];
    const float* Wo_i  = (const float*)d_in[9];
    const float* bo_r  = (const float*)d_in[10];
    const float* bo_i  = (const float*)d_in[11];
    const float* ln1_gr = (const float*)d_in[12];
    const float* ln1_gi = (const float*)d_in[13];
    const float* ln1_br = (const float*)d_in[14];
    const float* ln1_bi = (const float*)d_in[15];
    const float* ln2_gr = (const float*)d_in[16];
    const float* ln2_gi = (const float*)d_in[17];
    const float* ln2_br = (const float*)d_in[18];
    const float* ln2_bi = (const float*)d_in[19];
    const float* W1_r  = (const float*)d_in[20];
    const float* W1_i  = (const float*)d_in[21];
    const float* b1_r  = (const float*)d_in[22];
    const float* b1_i  = (const float*)d_in[23];
    const float* W2_r  = (const float*)d_in[24];
    const float* W2_i  = (const float*)d_in[25];
    const float* b2_r  = (const float*)d_in[26];
    const float* b2_i  = (const float*)d_in[27];
    const float* mod_b = (const float*)d_in[28];
    float* out = (float*)d_out;

    float *hr, *hi, *qr, *qi, *kr, *ki, *vr, *vi, *sb, *aor, *aoi, *ar, *ai, *fr, *fi;
    cudaGetSymbolAddress((void**)&hr,  g_hr);
    cudaGetSymbolAddress((void**)&hi,  g_hi);
    cudaGetSymbolAddress((void**)&qr,  g_qr);
    cudaGetSymbolAddress((void**)&qi,  g_qi);
    cudaGetSymbolAddress((void**)&kr,  g_kr);
    cudaGetSymbolAddress((void**)&ki,  g_ki);
    cudaGetSymbolAddress((void**)&vr,  g_vr);
    cudaGetSymbolAddress((void**)&vi,  g_vi);
    cudaGetSymbolAddress((void**)&sb,  g_s);
    cudaGetSymbolAddress((void**)&aor, g_aor);
    cudaGetSymbolAddress((void**)&aoi, g_aoi);
    cudaGetSymbolAddress((void**)&ar,  g_ar);
    cudaGetSymbolAddress((void**)&ai,  g_ai);
    cudaGetSymbolAddress((void**)&fr,  g_fr);
    cudaGetSymbolAddress((void**)&fi,  g_fi);

    // 1. LN1
    cln_kernel<<<Mn, 256>>>(x_r, x_i, ln1_gr, ln1_gi, ln1_br, ln1_bi, hr, hi);

    // 2. QKV projections (complex, no bias)
    dim3 gproj(Dn/64, Mn/128);
    cgemm_nt<<<gproj, 256>>>(hr, hi, Wq_r, Wq_i, qr, qi, Mn, Dn, Dn, nullptr, nullptr, nullptr, nullptr);
    cgemm_nt<<<gproj, 256>>>(hr, hi, Wk_r, Wk_i, kr, ki, Mn, Dn, Dn, nullptr, nullptr, nullptr, nullptr);
    cgemm_nt<<<gproj, 256>>>(hr, hi, Wv_r, Wv_i, vr, vi, Mn, Dn, Dn, nullptr, nullptr, nullptr, nullptr);

    // 3. RoPE on Q and K
    rope_kernel<<<(Bn*Ln*Hn*32)/256, 256>>>(qr, qi);
    rope_kernel<<<(Bn*Ln*Hn*32)/256, 256>>>(kr, ki);

    // 4. scores + softmax + attn@V
    scores_kernel<<<dim3(Ln/64, Ln/128, Bn*Hn), 256>>>(qr, qi, kr, ki, sb);
    softmax_kernel<<<Bn*Hn*Ln, 256>>>(sb);
    av_kernel<<<dim3(1, Ln/128, Bn*Hn), 256>>>(sb, vr, vi, aor, aoi);

    // 5. out projection + bias + residual(x)
    cgemm_nt<<<gproj, 256>>>(aor, aoi, Wo_r, Wo_i, ar, ai, Mn, Dn, Dn, bo_r, bo_i, x_r, x_i);

    // 6. LN2
    cln_kernel<<<Mn, 256>>>(ar, ai, ln2_gr, ln2_gi, ln2_br, ln2_bi, hr, hi);

    // 7. FC1 + bias
    cgemm_nt<<<dim3(HIDn/64, Mn/128), 256>>>(hr, hi, W1_r, W1_i, fr, fi, Mn, HIDn, Dn, b1_r, b1_i, nullptr, nullptr);

    // 8. ModReLU
    modrelu_kernel<<<(Mn*(size_t)HIDn)/256, 256>>>(fr, fi, mod_b);

    // 9. FC2 + bias + residual(ar/ai) -> output (real half, imag half)
    cgemm_nt<<<gproj, 256>>>(fr, fi, W2_r, W2_i, out, out + (size_t)Mn*Dn, Mn, Dn, HIDn, b2_r, b2_i, ar, ai);
}

// round 5
// speedup vs baseline: 2.5476x; 2.5476x over previous
#include <cuda_runtime.h>
#include <cstdint>
#include <math.h>

#define Bn   2
#define Ln   1024
#define Dn   1024
#define Hn   16
#define HDn  64
#define HIDn 4096
#define Mn   (Bn*Ln)        /* 2048 rows */
#define EPSc 1e-6f
#define SCALEc 0.125f       /* 64^-0.5 */

// ---------------- scratch (device globals; no runtime allocation) ----------
__device__ float g_hr[Mn*Dn],  g_hi[Mn*Dn];
__device__ float g_qr[Mn*Dn],  g_qi[Mn*Dn];
__device__ float g_kr[Mn*Dn],  g_ki[Mn*Dn];
__device__ float g_vr[Mn*Dn],  g_vi[Mn*Dn];
__device__ float g_s [Bn*Hn*Ln*Ln];          /* 128 MB scores/attn */
__device__ float g_aor[Mn*Dn], g_aoi[Mn*Dn];
__device__ float g_ar[Mn*Dn],  g_ai[Mn*Dn];
__device__ float g_fr[Mn*HIDn], g_fi[Mn*HIDn];

// ================= tf32 mma.sync helpers (baseline PTX, sm_80+) ============
__device__ __forceinline__ uint32_t f2tf32(float x) {
    uint32_t r;
    asm("cvt.rna.tf32.f32 %0, %1;" : "=r"(r) : "f"(x));
    return r;
}
__device__ __forceinline__ void st_tf32x4(float* p, float4 v) {
    uint4 u = make_uint4(f2tf32(v.x), f2tf32(v.y), f2tf32(v.z), f2tf32(v.w));
    *reinterpret_cast<uint4*>(p) = u;
}
#define MMA_TF32(d, a, b) \
    asm volatile("mma.sync.aligned.m16n8k8.row.col.f32.tf32.tf32.f32 " \
        "{%0,%1,%2,%3}, {%4,%5,%6,%7}, {%8,%9}, {%0,%1,%2,%3};" \
        : "+f"((d)[0]), "+f"((d)[1]), "+f"((d)[2]), "+f"((d)[3]) \
        : "r"((a)[0]), "r"((a)[1]), "r"((a)[2]), "r"((a)[3]), \
          "r"((b)[0]), "r"((b)[1]))

// ================= complex GEMM via tf32 tensor cores =======================
// C = A @ B^T (complex). A:[M,K], B:[N,K] row-major fp32.
// Block tile 128(M) x 64(N), BK=32. 8 warps: wm=wid&3 (m), wn=wid>>2 (n).
// Warp tile 32x32 = 2(m16) x 4(n8) m16n8k8 fragments.
//   accR += Ar*Br + (-Ai)*Bi ;  accI += Ar*Bi + Ai*Br
#define BMg 128
#define BNg 64
#define BKg 32
#define LDSK 36                     /* padded floats per row: conflict-free */
#define SMEM_GEMM ((BMg*LDSK*2 + BNg*LDSK*2) * 4)   /* 55296 B */

__global__ __launch_bounds__(256, 2)
void cmma_gemm(const float* __restrict__ Ar, const float* __restrict__ Ai,
               const float* __restrict__ Br, const float* __restrict__ Bi,
               float* __restrict__ Cr, float* __restrict__ Ci,
               int M, int N, int K,
               const float* __restrict__ biasr, const float* __restrict__ biasi,
               const float* __restrict__ resr,  const float* __restrict__ resi)
{
    extern __shared__ float sm[];
    float* Asr = sm;                       // [128][36]
    float* Asi = Asr + BMg*LDSK;
    float* Bsr = Asi + BMg*LDSK;           // [64][36]
    float* Bsi = Bsr + BNg*LDSK;

    const int tid  = threadIdx.x;
    const int wid  = tid >> 5, lane = tid & 31;
    const int g    = lane >> 2, t4 = lane & 3;
    const int wm   = wid & 3,  wn = wid >> 2;
    const int bm   = blockIdx.y * BMg, bn = blockIdx.x * BNg;

    float accR[2][4][4], accI[2][4][4];
#pragma unroll
    for (int mt = 0; mt < 2; mt++)
#pragma unroll
        for (int nt = 0; nt < 4; nt++)
#pragma unroll
            for (int r = 0; r < 4; r++) { accR[mt][nt][r] = 0.f; accI[mt][nt][r] = 0.f; }

    for (int k0 = 0; k0 < K; k0 += BKg) {
        // ---- stage A (128x32) and B (64x32), converting fp32 -> tf32 ------
#pragma unroll
        for (int j = 0; j < 4; j++) {
            int f = tid + j * 256;                 // 0..1023
            int row = f >> 3, c4 = f & 7;
            size_t ga = (size_t)(bm + row) * K + k0 + c4 * 4;
            st_tf32x4(Asr + row*LDSK + c4*4, *(const float4*)(Ar + ga));
            st_tf32x4(Asi + row*LDSK + c4*4, *(const float4*)(Ai + ga));
        }
#pragma unroll
        for (int j = 0; j < 2; j++) {
            int f = tid + j * 256;                 // 0..511
            int row = f >> 3, c4 = f & 7;
            size_t gb = (size_t)(bn + row) * K + k0 + c4 * 4;
            st_tf32x4(Bsr + row*LDSK + c4*4, *(const float4*)(Br + gb));
            st_tf32x4(Bsi + row*LDSK + c4*4, *(const float4*)(Bi + gb));
        }
        __syncthreads();

        // ---- 4 k-steps of m16n8k8 ----------------------------------------
#pragma unroll
        for (int ks = 0; ks < 4; ks++) {
            const int kc = ks * 8;
            uint32_t afr[2][4], afi[2][4];
#pragma unroll
            for (int mt = 0; mt < 2; mt++) {
                int r0 = (wm*32 + mt*16 + g) * LDSK + kc + t4;
                int r1 = r0 + 8 * LDSK;
                afr[mt][0] = __float_as_uint(Asr[r0]);
                afr[mt][1] = __float_as_uint(Asr[r1]);
                afr[mt][2] = __float_as_uint(Asr[r0 + 4]);
                afr[mt][3] = __float_as_uint(Asr[r1 + 4]);
                afi[mt][0] = __float_as_uint(Asi[r0]);
                afi[mt][1] = __float_as_uint(Asi[r1]);
                afi[mt][2] = __float_as_uint(Asi[r0 + 4]);
                afi[mt][3] = __float_as_uint(Asi[r1 + 4]);
            }
            uint32_t bfr[4][2], bfi[4][2];
#pragma unroll
            for (int nt = 0; nt < 4; nt++) {
                int q0 = (wn*32 + nt*8 + g) * LDSK + kc + t4;
                bfr[nt][0] = __float_as_uint(Bsr[q0]);
                bfr[nt][1] = __float_as_uint(Bsr[q0 + 4]);
                bfi[nt][0] = __float_as_uint(Bsi[q0]);
                bfi[nt][1] = __float_as_uint(Bsi[q0 + 4]);
            }
#pragma unroll
            for (int mt = 0; mt < 2; mt++) {
                uint32_t afn[4];
#pragma unroll
                for (int r = 0; r < 4; r++) afn[r] = afi[mt][r] ^ 0x80000000u;
#pragma unroll
                for (int nt = 0; nt < 4; nt++) {
                    MMA_TF32(accR[mt][nt], afr[mt], bfr[nt]);
                    MMA_TF32(accR[mt][nt], afn,     bfi[nt]);
                    MMA_TF32(accI[mt][nt], afr[mt], bfi[nt]);
                    MMA_TF32(accI[mt][nt], afi[mt], bfr[nt]);
                }
            }
        }
        __syncthreads();
    }

    // ---- epilogue: bias / residual / store --------------------------------
#pragma unroll
    for (int mt = 0; mt < 2; mt++) {
#pragma unroll
        for (int rh = 0; rh < 2; rh++) {
            const int row = bm + wm*32 + mt*16 + g + rh*8;
#pragma unroll
            for (int nt = 0; nt < 4; nt++) {
                const int col = bn + wn*32 + nt*8 + 2*t4;
                float vr0 = accR[mt][nt][rh*2],   vr1 = accR[mt][nt][rh*2+1];
                float vi0 = accI[mt][nt][rh*2],   vi1 = accI[mt][nt][rh*2+1];
                if (biasr) {
                    vr0 += biasr[col]; vr1 += biasr[col+1];
                    vi0 += biasi[col]; vi1 += biasi[col+1];
                }
                if (resr) {
                    const float2 rr = *(const float2*)(resr + (size_t)row*N + col);
                    const float2 ri = *(const float2*)(resi + (size_t)row*N + col);
                    vr0 += rr.x; vr1 += rr.y; vi0 += ri.x; vi1 += ri.y;
                }
                *(float2*)(Cr + (size_t)row*N + col) = make_float2(vr0, vr1);
                *(float2*)(Ci + (size_t)row*N + col) = make_float2(vi0, vi1);
            }
        }
    }
}

// ---------------- complex layernorm ----------------------------------------
__global__ void cln_kernel(const float* __restrict__ xr, const float* __restrict__ xi,
                           const float* __restrict__ gr, const float* __restrict__ gi,
                           const float* __restrict__ bre, const float* __restrict__ bim,
                           float* __restrict__ outr, float* __restrict__ outi)
{
    int row = blockIdx.x;
    const float* pr = xr + (size_t)row * Dn;
    const float* pi = xi + (size_t)row * Dn;
    __shared__ float s1[256], s2[256];
    int tid = threadIdx.x;
    float sr = 0.f, si = 0.f;
    for (int j = tid; j < Dn; j += 256) { sr += pr[j]; si += pi[j]; }
    s1[tid] = sr; s2[tid] = si;
    __syncthreads();
    for (int o = 128; o > 0; o >>= 1) {
        if (tid < o) { s1[tid] += s1[tid+o]; s2[tid] += s2[tid+o]; }
        __syncthreads();
    }
    float mr = s1[0] * (1.f/Dn), mi = s2[0] * (1.f/Dn);
    __syncthreads();
    float v = 0.f;
    for (int j = tid; j < Dn; j += 256) {
        float cr = pr[j] - mr, ci = pi[j] - mi;
        v += cr*cr + ci*ci;
    }
    s1[tid] = v;
    __syncthreads();
    for (int o = 128; o > 0; o >>= 1) {
        if (tid < o) s1[tid] += s1[tid+o];
        __syncthreads();
    }
    float inv = rsqrtf(s1[0] * (1.f/Dn) + EPSc);
    for (int j = tid; j < Dn; j += 256) {
        float nr = (pr[j]-mr)*inv, ni = (pi[j]-mi)*inv;
        outr[(size_t)row*Dn + j] = nr*gr[j] - ni*gi[j] + bre[j];
        outi[(size_t)row*Dn + j] = nr*gi[j] + ni*gr[j] + bim[j];
    }
}

// ---------------- RoPE (in place, per (b,l,h, pair j<32)) ------------------
__global__ void rope_kernel(float* __restrict__ xr, float* __restrict__ xi)
{
    int idx = blockIdx.x * blockDim.x + threadIdx.x;   // Bn*Ln*Hn*32 threads
    int j = idx & 31;
    int t = idx >> 5;
    int h = t & (Hn-1); t >>= 4;
    int l = t & (Ln-1);
    int b = t >> 10;
    size_t base = ((size_t)(b*Ln + l)) * Dn + h * HDn;
    double invf = exp(-((double)(2*j) / (double)HDn) * 9.210340371976184); // ln(1e4)
    double th = (double)l * invf;
    double sd, cd;
    sincos(th, &sd, &cd);
    float c = (float)cd, s = (float)sd;
    float a0 = xr[base+j], a1 = xr[base+j+32];
    xr[base+j]    = a0*c - a1*s;
    xr[base+j+32] = a1*c + a0*s;
    float b0 = xi[base+j], b1 = xi[base+j+32];
    xi[base+j]    = b0*c - b1*s;
    xi[base+j+32] = b1*c + b0*s;
}

// ---------------- scores = (Qr Kr^T + Qi Ki^T) * SCALE, causal-block-skip ---
__global__ __launch_bounds__(256, 2)
void scores_kernel(const float* __restrict__ Q_r, const float* __restrict__ Q_i,
                   const float* __restrict__ K_r, const float* __restrict__ K_i,
                   float* __restrict__ S)
{
    int bh = blockIdx.z;
    int b = bh >> 4, h = bh & 15;
    int bm = blockIdx.y * 128, bn = blockIdx.x * 64;
    if (bn > bm + 127) return;                      // fully masked block
    const size_t off = (size_t)b * Ln * Dn + (size_t)h * HDn;
    const float* Ar = Q_r + off; const float* Ai = Q_i + off;
    const float* Br = K_r + off; const float* Bi = K_i + off;
    __shared__ float Asr[16][132], Asi[16][132], Bsr[16][68], Bsi[16][68];
    const int tid = threadIdx.x;
    const int tx = tid & 15, ty = tid >> 4;
    const int r0 = ty * 8, c0 = tx * 4;
    const int lm = tid >> 2, lk = (tid & 3) * 4;
    float acc[8][4];
#pragma unroll
    for (int i = 0; i < 8; i++)
#pragma unroll
        for (int j = 0; j < 4; j++) acc[i][j] = 0.f;

#pragma unroll
    for (int k0 = 0; k0 < HDn; k0 += 16) {
#pragma unroll
        for (int p = 0; p < 2; p++) {
            int row = bm + p*64 + lm;
            float4 a4r = *(const float4*)(Ar + (size_t)row * Dn + k0 + lk);
            float4 a4i = *(const float4*)(Ai + (size_t)row * Dn + k0 + lk);
            int col = p*64 + lm;
            Asr[lk+0][col] = a4r.x; Asr[lk+1][col] = a4r.y;
            Asr[lk+2][col] = a4r.z; Asr[lk+3][col] = a4r.w;
            Asi[lk+0][col] = a4i.x; Asi[lk+1][col] = a4i.y;
            Asi[lk+2][col] = a4i.z; Asi[lk+3][col] = a4i.w;
        }
        {
            int row = bn + lm;
            float4 b4r = *(const float4*)(Br + (size_t)row * Dn + k0 + lk);
            float4 b4i = *(const float4*)(Bi + (size_t)row * Dn + k0 + lk);
            Bsr[lk+0][lm] = b4r.x; Bsr[lk+1][lm] = b4r.y;
            Bsr[lk+2][lm] = b4r.z; Bsr[lk+3][lm] = b4r.w;
            Bsi[lk+0][lm] = b4i.x; Bsi[lk+1][lm] = b4i.y;
            Bsi[lk+2][lm] = b4i.z; Bsi[lk+3][lm] = b4i.w;
        }
        __syncthreads();
#pragma unroll
        for (int kk = 0; kk < 16; kk++) {
            float ar[8], ai[8], br[4], bi[4];
            *(float4*)&ar[0] = *(const float4*)&Asr[kk][r0];
            *(float4*)&ar[4] = *(const float4*)&Asr[kk][r0+4];
            *(float4*)&ai[0] = *(const float4*)&Asi[kk][r0];
            *(float4*)&ai[4] = *(const float4*)&Asi[kk][r0+4];
            *(float4*)&br[0] = *(const float4*)&Bsr[kk][c0];
            *(float4*)&bi[0] = *(const float4*)&Bsi[kk][c0];
#pragma unroll
            for (int i = 0; i < 8; i++)
#pragma unroll
                for (int j = 0; j < 4; j++) {
                    acc[i][j] = fmaf(ar[i], br[j], acc[i][j]);
                    acc[i][j] = fmaf(ai[i], bi[j], acc[i][j]);
                }
        }
        __syncthreads();
    }
#pragma unroll
    for (int i = 0; i < 8; i++) {
        int row = bm + r0 + i;
#pragma unroll
        for (int j = 0; j < 4; j++) {
            int col = bn + c0 + j;
            S[((size_t)bh * Ln + row) * Ln + col] = acc[i][j] * SCALEc;
        }
    }
}

// ---------------- causal softmax (in place), zeros above diagonal -----------
__global__ void softmax_kernel(float* __restrict__ S)
{
    int row = blockIdx.x;                 // 0 .. B*H*L-1
    int l = row & (Ln - 1);
    float* p = S + (size_t)row * Ln;
    __shared__ float red[256];
    int tid = threadIdx.x;
    float m = -1e30f;
    for (int j = tid; j <= l; j += 256) m = fmaxf(m, p[j]);
    red[tid] = m; __syncthreads();
    for (int o = 128; o > 0; o >>= 1) {
        if (tid < o) red[tid] = fmaxf(red[tid], red[tid+o]);
        __syncthreads();
    }
    m = red[0]; __syncthreads();
    float s = 0.f;
    for (int j = tid; j <= l; j += 256) s += expf(p[j] - m);
    red[tid] = s; __syncthreads();
    for (int o = 128; o > 0; o >>= 1) {
        if (tid < o) red[tid] += red[tid+o];
        __syncthreads();
    }
    float inv = 1.f / red[0];
    for (int j = tid; j < Ln; j += 256)
        p[j] = (j <= l) ? expf(p[j] - m) * inv : 0.f;
}

// ---------------- out = attn @ V (both r and i), causal k-loop truncation ---
__global__ __launch_bounds__(256, 2)
void av_kernel(const float* __restrict__ S,
               const float* __restrict__ V_r, const float* __restrict__ V_i,
               float* __restrict__ Or, float* __restrict__ Oi)
{
    int bh = blockIdx.z;
    int b = bh >> 4, h = bh & 15;
    int bm = blockIdx.y * 128;
    const float* P = S + (size_t)bh * Ln * Ln;
    const size_t voff = (size_t)b * Ln * Dn + (size_t)h * HDn;
    __shared__ float As[16][132], Bsr[16][68], Bsi[16][68];
    const int tid = threadIdx.x;
    const int tx = tid & 15, ty = tid >> 4;
    const int r0 = ty * 8, c0 = tx * 4;
    const int lm = tid >> 2, lk = (tid & 3) * 4;
    const int vrow = tid >> 4, vc4 = (tid & 15) * 4;
    float cr[8][4], ci[8][4];
#pragma unroll
    for (int i = 0; i < 8; i++)
#pragma unroll
        for (int j = 0; j < 4; j++) { cr[i][j] = 0.f; ci[i][j] = 0.f; }

    int kmax = bm + 128;                   // rows in this block see m <= bm+127
    for (int k0 = 0; k0 < kmax; k0 += 16) {
#pragma unroll
        for (int p = 0; p < 2; p++) {
            int row = bm + p*64 + lm;
            float4 a4 = *(const float4*)(P + (size_t)row * Ln + k0 + lk);
            int col = p*64 + lm;
            As[lk+0][col] = a4.x; As[lk+1][col] = a4.y;
            As[lk+2][col] = a4.z; As[lk+3][col] = a4.w;
        }
        {
            float4 v4r = *(const float4*)(V_r + voff + (size_t)(k0 + vrow) * Dn + vc4);
            float4 v4i = *(const float4*)(V_i + voff + (size_t)(k0 + vrow) * Dn + vc4);
            Bsr[vrow][vc4+0] = v4r.x; Bsr[vrow][vc4+1] = v4r.y;
            Bsr[vrow][vc4+2] = v4r.z; Bsr[vrow][vc4+3] = v4r.w;
            Bsi[vrow][vc4+0] = v4i.x; Bsi[vrow][vc4+1] = v4i.y;
            Bsi[vrow][vc4+2] = v4i.z; Bsi[vrow][vc4+3] = v4i.w;
        }
        __syncthreads();
#pragma unroll
        for (int kk = 0; kk < 16; kk++) {
            float a[8], br[4], bi[4];
            *(float4*)&a[0] = *(const float4*)&As[kk][r0];
            *(float4*)&a[4] = *(const float4*)&As[kk][r0+4];
            *(float4*)&br[0] = *(const float4*)&Bsr[kk][c0];
            *(float4*)&bi[0] = *(const float4*)&Bsi[kk][c0];
#pragma unroll
            for (int i = 0; i < 8; i++)
#pragma unroll
                for (int j = 0; j < 4; j++) {
                    cr[i][j] = fmaf(a[i], br[j], cr[i][j]);
                    ci[i][j] = fmaf(a[i], bi[j], ci[i][j]);
                }
        }
        __syncthreads();
    }
#pragma unroll
    for (int i = 0; i < 8; i++) {
        int row = bm + r0 + i;
#pragma unroll
        for (int j = 0; j < 4; j++) {
            Or[voff + (size_t)row * Dn + c0 + j] = cr[i][j];
            Oi[voff + (size_t)row * Dn + c0 + j] = ci[i][j];
        }
    }
}

// ---------------- ModReLU ---------------------------------------------------
__global__ void modrelu_kernel(float* __restrict__ fr, float* __restrict__ fi,
                               const float* __restrict__ mb)
{
    size_t idx = (size_t)blockIdx.x * blockDim.x + threadIdx.x;
    int col = (int)(idx & (HIDn - 1));
    float r = fr[idx], i = fi[idx];
    float mag = sqrtf(r*r + i*i);
    float safe = mag > 0.f ? mag : 1.f;
    float act = fmaxf(mag + mb[col], 0.f);
    float fac = act / safe;
    fr[idx] = r * fac;
    fi[idx] = i * fac;
}

// ---------------- launch ----------------------------------------------------
extern "C" void kernel_launch(void* const* d_in, const int* in_sizes, int n_in,
                              void* d_out, int out_size)
{
    const float* x_r   = (const float*)d_in[0];
    const float* x_i   = (const float*)d_in[1];
    const float* Wq_r  = (const float*)d_in[2];
    const float* Wq_i  = (const float*)d_in[3];
    const float* Wk_r  = (const float*)d_in[4];
    const float* Wk_i  = (const float*)d_in[5];
    const float* Wv_r  = (const float*)d_in[6];
    const float* Wv_i  = (const float*)d_in[7];
    const float* Wo_r  = (const float*)d_in[8];
    const float* Wo_i  = (const float*)d_in[9];
    const float* bo_r  = (const float*)d_in[10];
    const float* bo_i  = (const float*)d_in[11];
    const float* ln1_gr = (const float*)d_in[12];
    const float* ln1_gi = (const float*)d_in[13];
    const float* ln1_br = (const float*)d_in[14];
    const float* ln1_bi = (const float*)d_in[15];
    const float* ln2_gr = (const float*)d_in[16];
    const float* ln2_gi = (const float*)d_in[17];
    const float* ln2_br = (const float*)d_in[18];
    const float* ln2_bi = (const float*)d_in[19];
    const float* W1_r  = (const float*)d_in[20];
    const float* W1_i  = (const float*)d_in[21];
    const float* b1_r  = (const float*)d_in[22];
    const float* b1_i  = (const float*)d_in[23];
    const float* W2_r  = (const float*)d_in[24];
    const float* W2_i  = (const float*)d_in[25];
    const float* b2_r  = (const float*)d_in[26];
    const float* b2_i  = (const float*)d_in[27];
    const float* mod_b = (const float*)d_in[28];
    float* out = (float*)d_out;

    float *hr, *hi, *qr, *qi, *kr, *ki, *vr, *vi, *sb, *aor, *aoi, *ar, *ai, *fr, *fi;
    cudaGetSymbolAddress((void**)&hr,  g_hr);
    cudaGetSymbolAddress((void**)&hi,  g_hi);
    cudaGetSymbolAddress((void**)&qr,  g_qr);
    cudaGetSymbolAddress((void**)&qi,  g_qi);
    cudaGetSymbolAddress((void**)&kr,  g_kr);
    cudaGetSymbolAddress((void**)&ki,  g_ki);
    cudaGetSymbolAddress((void**)&vr,  g_vr);
    cudaGetSymbolAddress((void**)&vi,  g_vi);
    cudaGetSymbolAddress((void**)&sb,  g_s);
    cudaGetSymbolAddress((void**)&aor, g_aor);
    cudaGetSymbolAddress((void**)&aoi, g_aoi);
    cudaGetSymbolAddress((void**)&ar,  g_ar);
    cudaGetSymbolAddress((void**)&ai,  g_ai);
    cudaGetSymbolAddress((void**)&fr,  g_fr);
    cudaGetSymbolAddress((void**)&fi,  g_fi);

    cudaFuncSetAttribute(cmma_gemm, cudaFuncAttributeMaxDynamicSharedMemorySize, SMEM_GEMM);

    // 1. LN1
    cln_kernel<<<Mn, 256>>>(x_r, x_i, ln1_gr, ln1_gi, ln1_br, ln1_bi, hr, hi);

    // 2. QKV projections (complex, no bias) — tf32 mma.sync
    dim3 gproj(Dn/BNg, Mn/BMg);
    cmma_gemm<<<gproj, 256, SMEM_GEMM>>>(hr, hi, Wq_r, Wq_i, qr, qi, Mn, Dn, Dn, nullptr, nullptr, nullptr, nullptr);
    cmma_gemm<<<gproj, 256, SMEM_GEMM>>>(hr, hi, Wk_r, Wk_i, kr, ki, Mn, Dn, Dn, nullptr, nullptr, nullptr, nullptr);
    cmma_gemm<<<gproj, 256, SMEM_GEMM>>>(hr, hi, Wv_r, Wv_i, vr, vi, Mn, Dn, Dn, nullptr, nullptr, nullptr, nullptr);

    // 3. RoPE on Q and K
    rope_kernel<<<(Bn*Ln*Hn*32)/256, 256>>>(qr, qi);
    rope_kernel<<<(Bn*Ln*Hn*32)/256, 256>>>(kr, ki);

    // 4. scores + softmax + attn@V (SIMT for now)
    scores_kernel<<<dim3(Ln/64, Ln/128, Bn*Hn), 256>>>(qr, qi, kr, ki, sb);
    softmax_kernel<<<Bn*Hn*Ln, 256>>>(sb);
    av_kernel<<<dim3(1, Ln/128, Bn*Hn), 256>>>(sb, vr, vi, aor, aoi);

    // 5. out projection + bias + residual(x)
    cmma_gemm<<<gproj, 256, SMEM_GEMM>>>(aor, aoi, Wo_r, Wo_i, ar, ai, Mn, Dn, Dn, bo_r, bo_i, x_r, x_i);

    // 6. LN2
    cln_kernel<<<Mn, 256>>>(ar, ai, ln2_gr, ln2_gi, ln2_br, ln2_bi, hr, hi);

    // 7. FC1 + bias
    cmma_gemm<<<dim3(HIDn/BNg, Mn/BMg), 256, SMEM_GEMM>>>(hr, hi, W1_r, W1_i, fr, fi, Mn, HIDn, Dn, b1_r, b1_i, nullptr, nullptr);

    // 8. ModReLU
    modrelu_kernel<<<(Mn*(size_t)HIDn)/256, 256>>>(fr, fi, mod_b);

    // 9. FC2 + bias + residual(ar/ai) -> output (real half, imag half)
    cmma_gemm<<<gproj, 256, SMEM_GEMM>>>(fr, fi, W2_r, W2_i, out, out + (size_t)Mn*Dn, Mn, Dn, HIDn, b2_r, b2_i, ar, ai);
}

// round 6
// speedup vs baseline: 2.7677x; 1.0864x over previous
#include <cuda_runtime.h>
#include <cstdint>
#include <math.h>

#define Bn   2
#define Ln   1024
#define Dn   1024
#define Hn   16
#define HDn  64
#define HIDn 4096
#define Mn   (Bn*Ln)        /* 2048 rows */
#define EPSc 1e-6f
#define SCALEc 0.125f       /* 64^-0.5 */

// ---------------- scratch (device globals; no runtime allocation) ----------
__device__ float g_hr[Mn*Dn],  g_hi[Mn*Dn];
__device__ float g_qr[Mn*Dn],  g_qi[Mn*Dn];
__device__ float g_kr[Mn*Dn],  g_ki[Mn*Dn];
__device__ float g_vr[Mn*Dn],  g_vi[Mn*Dn];
__device__ float g_s [Bn*Hn*Ln*Ln];          /* 128 MB scores/attn */
__device__ float g_aor[Mn*Dn], g_aoi[Mn*Dn];
__device__ float g_ar[Mn*Dn],  g_ai[Mn*Dn];
__device__ float g_fr[Mn*HIDn], g_fi[Mn*HIDn];

// ================= helpers (baseline PTX only: sm_80-level) =================
__device__ __forceinline__ uint32_t smem_u32(const void* p) {
    uint32_t a;
    asm("{ .reg .u64 t; cvta.to.shared.u64 t, %1; cvt.u32.u64 %0, t; }" : "=r"(a) : "l"(p));
    return a;
}
#define CP16(dst_u32, src_ptr) \
    asm volatile("cp.async.cg.shared.global [%0], [%1], 16;" :: "r"(dst_u32), "l"(src_ptr) : "memory")
#define CP_COMMIT() asm volatile("cp.async.commit_group;" ::: "memory")
#define CP_WAIT1()  asm volatile("cp.async.wait_group 1;" ::: "memory")

__device__ __forceinline__ uint32_t f2tf32(float x) {
    uint32_t r;
    asm("cvt.rna.tf32.f32 %0, %1;" : "=r"(r) : "f"(x));
    return r;
}
__device__ __forceinline__ void st_tf32x4(float* p, float4 v) {
    uint4 u = make_uint4(f2tf32(v.x), f2tf32(v.y), f2tf32(v.z), f2tf32(v.w));
    *reinterpret_cast<uint4*>(p) = u;
}
#define MMA_TF32(d, a, b) \
    asm volatile("mma.sync.aligned.m16n8k8.row.col.f32.tf32.tf32.f32 " \
        "{%0,%1,%2,%3}, {%4,%5,%6,%7}, {%8,%9}, {%0,%1,%2,%3};" \
        : "+f"((d)[0]), "+f"((d)[1]), "+f"((d)[2]), "+f"((d)[3]) \
        : "r"((a)[0]), "r"((a)[1]), "r"((a)[2]), "r"((a)[3]), \
          "r"((b)[0]), "r"((b)[1]))

// ================= complex GEMM, cp.async 2-stage pipeline ==================
// C = A @ B^T (complex). A:[M,K], B:[N,K] row-major fp32.
// Block 128x64, BK=32. 8 warps (4m x 2n), warp tile 32x32 (2x4 m16n8k8).
#define BMg 128
#define BNg 64
#define BKg 32
#define LDSK 36
#define STG_FLOATS (BMg*LDSK*2 + BNg*LDSK*2)   /* 13824 floats */
#define SMEM_GEMM  (2*STG_FLOATS*4)            /* 110592 B */

__global__ __launch_bounds__(256, 1)
void cmma_gemm(const float* __restrict__ Ar, const float* __restrict__ Ai,
               const float* __restrict__ Br, const float* __restrict__ Bi,
               float* __restrict__ Cr, float* __restrict__ Ci,
               int M, int N, int K,
               const float* __restrict__ biasr, const float* __restrict__ biasi,
               const float* __restrict__ resr,  const float* __restrict__ resi)
{
    extern __shared__ float sm[];
    const uint32_t sb = smem_u32(sm);
    const int tid  = threadIdx.x;
    const int wid  = tid >> 5, lane = tid & 31;
    const int g    = lane >> 2, t4 = lane & 3;
    const int wm   = wid & 3,  wn = wid >> 2;
    const int bm   = blockIdx.y * BMg, bn = blockIdx.x * BNg;
    const int row8 = tid >> 3, c4b = (tid & 7) * 4;

    float accR[2][4][4], accI[2][4][4];
#pragma unroll
    for (int mt = 0; mt < 2; mt++)
#pragma unroll
        for (int nt = 0; nt < 4; nt++)
#pragma unroll
            for (int r = 0; r < 4; r++) { accR[mt][nt][r] = 0.f; accI[mt][nt][r] = 0.f; }

    const int nch = K / BKg;
    auto prefetch = [&](int ch) {
        const int s = ch & 1;
        const uint32_t dst = sb + (uint32_t)(s * STG_FLOATS) * 4u;
        const int k0 = ch * BKg;
#pragma unroll
        for (int j = 0; j < 4; j++) {
            const int row = row8 + j * 32;
            const uint32_t o = (uint32_t)(row * LDSK + c4b) * 4u;
            const size_t ga = (size_t)(bm + row) * K + k0 + c4b;
            CP16(dst + o,                            Ar + ga);
            CP16(dst + (uint32_t)(BMg*LDSK)*4u + o,  Ai + ga);
        }
#pragma unroll
        for (int j = 0; j < 2; j++) {
            const int row = row8 + j * 32;
            const uint32_t o = (uint32_t)(row * LDSK + c4b) * 4u;
            const size_t gb = (size_t)(bn + row) * K + k0 + c4b;
            CP16(dst + (uint32_t)(2*BMg*LDSK)*4u + o,            Br + gb);
            CP16(dst + (uint32_t)(2*BMg*LDSK + BNg*LDSK)*4u + o, Bi + gb);
        }
    };

    prefetch(0);
    CP_COMMIT();
    for (int ch = 0; ch < nch; ch++) {
        if (ch + 1 < nch) prefetch(ch + 1);
        CP_COMMIT();
        CP_WAIT1();
        __syncthreads();
        const float* Asr = sm + (ch & 1) * STG_FLOATS;
        const float* Asi = Asr + BMg*LDSK;
        const float* Bsr = Asi + BMg*LDSK;
        const float* Bsi = Bsr + BNg*LDSK;
#pragma unroll
        for (int ks = 0; ks < 4; ks++) {
            const int kc = ks * 8;
            uint32_t afr[2][4], afi[2][4];
#pragma unroll
            for (int mt = 0; mt < 2; mt++) {
                const int r0 = (wm*32 + mt*16 + g) * LDSK + kc + t4;
                const int r1 = r0 + 8 * LDSK;
                afr[mt][0] = __float_as_uint(Asr[r0]);
                afr[mt][1] = __float_as_uint(Asr[r1]);
                afr[mt][2] = __float_as_uint(Asr[r0 + 4]);
                afr[mt][3] = __float_as_uint(Asr[r1 + 4]);
                afi[mt][0] = __float_as_uint(Asi[r0]);
                afi[mt][1] = __float_as_uint(Asi[r1]);
                afi[mt][2] = __float_as_uint(Asi[r0 + 4]);
                afi[mt][3] = __float_as_uint(Asi[r1 + 4]);
            }
            uint32_t bfr[4][2], bfi[4][2];
#pragma unroll
            for (int nt = 0; nt < 4; nt++) {
                const int q0 = (wn*32 + nt*8 + g) * LDSK + kc + t4;
                bfr[nt][0] = __float_as_uint(Bsr[q0]);
                bfr[nt][1] = __float_as_uint(Bsr[q0 + 4]);
                bfi[nt][0] = __float_as_uint(Bsi[q0]);
                bfi[nt][1] = __float_as_uint(Bsi[q0 + 4]);
            }
#pragma unroll
            for (int mt = 0; mt < 2; mt++) {
                uint32_t afn[4];
#pragma unroll
                for (int r = 0; r < 4; r++) afn[r] = afi[mt][r] ^ 0x80000000u;
#pragma unroll
                for (int nt = 0; nt < 4; nt++) {
                    MMA_TF32(accR[mt][nt], afr[mt], bfr[nt]);
                    MMA_TF32(accR[mt][nt], afn,     bfi[nt]);
                    MMA_TF32(accI[mt][nt], afr[mt], bfi[nt]);
                    MMA_TF32(accI[mt][nt], afi[mt], bfr[nt]);
                }
            }
        }
        __syncthreads();
    }

#pragma unroll
    for (int mt = 0; mt < 2; mt++) {
#pragma unroll
        for (int rh = 0; rh < 2; rh++) {
            const int row = bm + wm*32 + mt*16 + g + rh*8;
#pragma unroll
            for (int nt = 0; nt < 4; nt++) {
                const int col = bn + wn*32 + nt*8 + 2*t4;
                float vr0 = accR[mt][nt][rh*2],   vr1 = accR[mt][nt][rh*2+1];
                float vi0 = accI[mt][nt][rh*2],   vi1 = accI[mt][nt][rh*2+1];
                if (biasr) {
                    vr0 += biasr[col]; vr1 += biasr[col+1];
                    vi0 += biasi[col]; vi1 += biasi[col+1];
                }
                if (resr) {
                    const float2 rr = *(const float2*)(resr + (size_t)row*N + col);
                    const float2 ri = *(const float2*)(resi + (size_t)row*N + col);
                    vr0 += rr.x; vr1 += rr.y; vi0 += ri.x; vi1 += ri.y;
                }
                *(float2*)(Cr + (size_t)row*N + col) = make_float2(vr0, vr1);
                *(float2*)(Ci + (size_t)row*N + col) = make_float2(vi0, vi1);
            }
        }
    }
}

// ================= scores via mma: S = (QrKr^T + QiKi^T)*SCALE ==============
// 128x128 block per (bh, tile). K = HD = 64, single stage, causal block-skip.
#define LDSQ 68
#define SMEM_SC (4*128*LDSQ*4)   /* 139264 B */

__global__ __launch_bounds__(256, 1)
void scores_mma(const float* __restrict__ Q_r, const float* __restrict__ Q_i,
                const float* __restrict__ K_r, const float* __restrict__ K_i,
                float* __restrict__ S)
{
    if (blockIdx.x > blockIdx.y) return;            // fully masked tile
    const int bh = blockIdx.z;
    const int bm = blockIdx.y * 128, bn = blockIdx.x * 128;
    const size_t off = (size_t)(bh >> 4) * Ln * Dn + (size_t)(bh & 15) * HDn;
    extern __shared__ float sm[];
    float* Qs_r = sm;
    float* Qs_i = Qs_r + 128*LDSQ;
    float* Ks_r = Qs_i + 128*LDSQ;
    float* Ks_i = Ks_r + 128*LDSQ;

    const int tid = threadIdx.x;
    const int wid = tid >> 5, lane = tid & 31;
    const int g = lane >> 2, t4 = lane & 3;
    const int wm = wid & 3, wn = wid >> 2;       // 4m x 2n warps, warp tile 32x64

#pragma unroll
    for (int j = 0; j < 8; j++) {
        const int f = tid + j * 256;             // 0..2047
        const int row = f >> 4, c4 = (f & 15) * 4;
        const size_t gq = off + (size_t)(bm + row) * Dn + c4;
        const size_t gk = off + (size_t)(bn + row) * Dn + c4;
        st_tf32x4(Qs_r + row*LDSQ + c4, *(const float4*)(Q_r + gq));
        st_tf32x4(Qs_i + row*LDSQ + c4, *(const float4*)(Q_i + gq));
        st_tf32x4(Ks_r + row*LDSQ + c4, *(const float4*)(K_r + gk));
        st_tf32x4(Ks_i + row*LDSQ + c4, *(const float4*)(K_i + gk));
    }
    __syncthreads();

    float acc[2][8][4];
#pragma unroll
    for (int mt = 0; mt < 2; mt++)
#pragma unroll
        for (int nt = 0; nt < 8; nt++)
#pragma unroll
            for (int r = 0; r < 4; r++) acc[mt][nt][r] = 0.f;

#pragma unroll
    for (int ks = 0; ks < 8; ks++) {
        const int kc = ks * 8;
        uint32_t aqr[2][4], aqi[2][4];
#pragma unroll
        for (int mt = 0; mt < 2; mt++) {
            const int r0 = (wm*32 + mt*16 + g) * LDSQ + kc + t4;
            const int r1 = r0 + 8 * LDSQ;
            aqr[mt][0] = __float_as_uint(Qs_r[r0]);
            aqr[mt][1] = __float_as_uint(Qs_r[r1]);
            aqr[mt][2] = __float_as_uint(Qs_r[r0 + 4]);
            aqr[mt][3] = __float_as_uint(Qs_r[r1 + 4]);
            aqi[mt][0] = __float_as_uint(Qs_i[r0]);
            aqi[mt][1] = __float_as_uint(Qs_i[r1]);
            aqi[mt][2] = __float_as_uint(Qs_i[r0 + 4]);
            aqi[mt][3] = __float_as_uint(Qs_i[r1 + 4]);
        }
#pragma unroll
        for (int nt = 0; nt < 8; nt++) {
            const int q0 = (wn*64 + nt*8 + g) * LDSQ + kc + t4;
            uint32_t bkr[2], bki[2];
            bkr[0] = __float_as_uint(Ks_r[q0]);
            bkr[1] = __float_as_uint(Ks_r[q0 + 4]);
            bki[0] = __float_as_uint(Ks_i[q0]);
            bki[1] = __float_as_uint(Ks_i[q0 + 4]);
#pragma unroll
            for (int mt = 0; mt < 2; mt++) {
                MMA_TF32(acc[mt][nt], aqr[mt], bkr);
                MMA_TF32(acc[mt][nt], aqi[mt], bki);
            }
        }
    }

#pragma unroll
    for (int mt = 0; mt < 2; mt++) {
#pragma unroll
        for (int rh = 0; rh < 2; rh++) {
            const int row = bm + wm*32 + mt*16 + g + rh*8;
#pragma unroll
            for (int nt = 0; nt < 8; nt++) {
                const int col = bn + wn*64 + nt*8 + 2*t4;
                *(float2*)(S + ((size_t)bh * Ln + row) * Ln + col) =
                    make_float2(acc[mt][nt][rh*2] * SCALEc, acc[mt][nt][rh*2+1] * SCALEc);
            }
        }
    }
}

// ================= AV via mma: O = P @ V (r and i) ==========================
// 128 rows x 64 cols per block, k chunks of 32, truncated at bm+128.
#define LDSP 36
#define LDSV 36
__global__ __launch_bounds__(256, 2)
void av_mma(const float* __restrict__ S,
            const float* __restrict__ V_r, const float* __restrict__ V_i,
            float* __restrict__ Or, float* __restrict__ Oi)
{
    const int bh = blockIdx.z;
    const int bm = blockIdx.y * 128;
    const float* P = S + (size_t)bh * Ln * Ln;
    const size_t voff = (size_t)(bh >> 4) * Ln * Dn + (size_t)(bh & 15) * HDn;

    __shared__ float Ps[128*LDSP];
    __shared__ float Vtr[64*LDSV], Vti[64*LDSV];

    const int tid = threadIdx.x;
    const int wid = tid >> 5, lane = tid & 31;
    const int g = lane >> 2, t4 = lane & 3;
    const int wm = wid & 3, wn = wid >> 2;     // 4m x 2n, warp tile 32x32

    float accR[2][4][4], accI[2][4][4];
#pragma unroll
    for (int mt = 0; mt < 2; mt++)
#pragma unroll
        for (int nt = 0; nt < 4; nt++)
#pragma unroll
            for (int r = 0; r < 4; r++) { accR[mt][nt][r] = 0.f; accI[mt][nt][r] = 0.f; }

    const int kmax = bm + 128;
    for (int k0 = 0; k0 < kmax; k0 += 32) {
        // stage P 128x32
#pragma unroll
        for (int j = 0; j < 4; j++) {
            const int f = tid + j * 256;
            const int row = f >> 3, c4 = (f & 7) * 4;
            st_tf32x4(Ps + row*LDSP + c4,
                      *(const float4*)(P + (size_t)(bm + row) * Ln + k0 + c4));
        }
        // stage V transposed: Vt[n][k] = V[k0+k][n]
#pragma unroll
        for (int j = 0; j < 2; j++) {
            const int f = tid + j * 256;         // 0..511
            const int kr = f >> 4, c4 = (f & 15) * 4;
            const float4 vr = *(const float4*)(V_r + voff + (size_t)(k0 + kr) * Dn + c4);
            const float4 vi = *(const float4*)(V_i + voff + (size_t)(k0 + kr) * Dn + c4);
            Vtr[(c4+0)*LDSV + kr] = __uint_as_float(f2tf32(vr.x));
            Vtr[(c4+1)*LDSV + kr] = __uint_as_float(f2tf32(vr.y));
            Vtr[(c4+2)*LDSV + kr] = __uint_as_float(f2tf32(vr.z));
            Vtr[(c4+3)*LDSV + kr] = __uint_as_float(f2tf32(vr.w));
            Vti[(c4+0)*LDSV + kr] = __uint_as_float(f2tf32(vi.x));
            Vti[(c4+1)*LDSV + kr] = __uint_as_float(f2tf32(vi.y));
            Vti[(c4+2)*LDSV + kr] = __uint_as_float(f2tf32(vi.z));
            Vti[(c4+3)*LDSV + kr] = __uint_as_float(f2tf32(vi.w));
        }
        __syncthreads();
#pragma unroll
        for (int ks = 0; ks < 4; ks++) {
            const int kc = ks * 8;
            uint32_t af[2][4];
#pragma unroll
            for (int mt = 0; mt < 2; mt++) {
                const int r0 = (wm*32 + mt*16 + g) * LDSP + kc + t4;
                const int r1 = r0 + 8 * LDSP;
                af[mt][0] = __float_as_uint(Ps[r0]);
                af[mt][1] = __float_as_uint(Ps[r1]);
                af[mt][2] = __float_as_uint(Ps[r0 + 4]);
                af[mt][3] = __float_as_uint(Ps[r1 + 4]);
            }
#pragma unroll
            for (int nt = 0; nt < 4; nt++) {
                const int q0 = (wn*32 + nt*8 + g) * LDSV + kc + t4;
                uint32_t bvr[2], bvi[2];
                bvr[0] = __float_as_uint(Vtr[q0]);
                bvr[1] = __float_as_uint(Vtr[q0 + 4]);
                bvi[0] = __float_as_uint(Vti[q0]);
                bvi[1] = __float_as_uint(Vti[q0 + 4]);
#pragma unroll
                for (int mt = 0; mt < 2; mt++) {
                    MMA_TF32(accR[mt][nt], af[mt], bvr);
                    MMA_TF32(accI[mt][nt], af[mt], bvi);
                }
            }
        }
        __syncthreads();
    }

#pragma unroll
    for (int mt = 0; mt < 2; mt++) {
#pragma unroll
        for (int rh = 0; rh < 2; rh++) {
            const int row = bm + wm*32 + mt*16 + g + rh*8;
#pragma unroll
            for (int nt = 0; nt < 4; nt++) {
                const int col = wn*32 + nt*8 + 2*t4;
                *(float2*)(Or + voff + (size_t)row*Dn + col) =
                    make_float2(accR[mt][nt][rh*2], accR[mt][nt][rh*2+1]);
                *(float2*)(Oi + voff + (size_t)row*Dn + col) =
                    make_float2(accI[mt][nt][rh*2], accI[mt][nt][rh*2+1]);
            }
        }
    }
}

// ---------------- complex layernorm ----------------------------------------
__global__ void cln_kernel(const float* __restrict__ xr, const float* __restrict__ xi,
                           const float* __restrict__ gr, const float* __restrict__ gi,
                           const float* __restrict__ bre, const float* __restrict__ bim,
                           float* __restrict__ outr, float* __restrict__ outi)
{
    int row = blockIdx.x;
    const float* pr = xr + (size_t)row * Dn;
    const float* pi = xi + (size_t)row * Dn;
    __shared__ float s1[256], s2[256];
    int tid = threadIdx.x;
    float sr = 0.f, si = 0.f;
    for (int j = tid; j < Dn; j += 256) { sr += pr[j]; si += pi[j]; }
    s1[tid] = sr; s2[tid] = si;
    __syncthreads();
    for (int o = 128; o > 0; o >>= 1) {
        if (tid < o) { s1[tid] += s1[tid+o]; s2[tid] += s2[tid+o]; }
        __syncthreads();
    }
    float mr = s1[0] * (1.f/Dn), mi = s2[0] * (1.f/Dn);
    __syncthreads();
    float v = 0.f;
    for (int j = tid; j < Dn; j += 256) {
        float cr = pr[j] - mr, ci = pi[j] - mi;
        v += cr*cr + ci*ci;
    }
    s1[tid] = v;
    __syncthreads();
    for (int o = 128; o > 0; o >>= 1) {
        if (tid < o) s1[tid] += s1[tid+o];
        __syncthreads();
    }
    float inv = rsqrtf(s1[0] * (1.f/Dn) + EPSc);
    for (int j = tid; j < Dn; j += 256) {
        float nr = (pr[j]-mr)*inv, ni = (pi[j]-mi)*inv;
        outr[(size_t)row*Dn + j] = nr*gr[j] - ni*gi[j] + bre[j];
        outi[(size_t)row*Dn + j] = nr*gi[j] + ni*gr[j] + bim[j];
    }
}

// ---------------- RoPE (in place) -------------------------------------------
__global__ void rope_kernel(float* __restrict__ xr, float* __restrict__ xi)
{
    int idx = blockIdx.x * blockDim.x + threadIdx.x;
    int j = idx & 31;
    int t = idx >> 5;
    int h = t & (Hn-1); t >>= 4;
    int l = t & (Ln-1);
    int b = t >> 10;
    size_t base = ((size_t)(b*Ln + l)) * Dn + h * HDn;
    double invf = exp(-((double)(2*j) / (double)HDn) * 9.210340371976184);
    double th = (double)l * invf;
    double sd, cd;
    sincos(th, &sd, &cd);
    float c = (float)cd, s = (float)sd;
    float a0 = xr[base+j], a1 = xr[base+j+32];
    xr[base+j]    = a0*c - a1*s;
    xr[base+j+32] = a1*c + a0*s;
    float b0 = xi[base+j], b1 = xi[base+j+32];
    xi[base+j]    = b0*c - b1*s;
    xi[base+j+32] = b1*c + b0*s;
}

// ---------------- causal softmax (in place), zeroed up to tile edge ---------
__global__ void softmax_kernel(float* __restrict__ S)
{
    int row = blockIdx.x;
    int l = row & (Ln - 1);
    float* p = S + (size_t)row * Ln;
    __shared__ float red[256];
    int tid = threadIdx.x;
    float m = -1e30f;
    for (int j = tid; j <= l; j += 256) m = fmaxf(m, p[j]);
    red[tid] = m; __syncthreads();
    for (int o = 128; o > 0; o >>= 1) {
        if (tid < o) red[tid] = fmaxf(red[tid], red[tid+o]);
        __syncthreads();
    }
    m = red[0]; __syncthreads();
    float s = 0.f;
    for (int j = tid; j <= l; j += 256) s += expf(p[j] - m);
    red[tid] = s; __syncthreads();
    for (int o = 128; o > 0; o >>= 1) {
        if (tid < o) red[tid] += red[tid+o];
        __syncthreads();
    }
    float inv = 1.f / red[0];
    const int lim = (l & ~127) + 128;         // av only reads cols < lim
    for (int j = tid; j < lim; j += 256)
        p[j] = (j <= l) ? expf(p[j] - m) * inv : 0.f;
}

// ---------------- ModReLU ---------------------------------------------------
__global__ void modrelu_kernel(float* __restrict__ fr, float* __restrict__ fi,
                               const float* __restrict__ mb)
{
    size_t idx = (size_t)blockIdx.x * blockDim.x + threadIdx.x;
    int col = (int)(idx & (HIDn - 1));
    float r = fr[idx], i = fi[idx];
    float mag = sqrtf(r*r + i*i);
    float safe = mag > 0.f ? mag : 1.f;
    float act = fmaxf(mag + mb[col], 0.f);
    float fac = act / safe;
    fr[idx] = r * fac;
    fi[idx] = i * fac;
}

// ---------------- launch ----------------------------------------------------
extern "C" void kernel_launch(void* const* d_in, const int* in_sizes, int n_in,
                              void* d_out, int out_size)
{
    const float* x_r   = (const float*)d_in[0];
    const float* x_i   = (const float*)d_in[1];
    const float* Wq_r  = (const float*)d_in[2];
    const float* Wq_i  = (const float*)d_in[3];
    const float* Wk_r  = (const float*)d_in[4];
    const float* Wk_i  = (const float*)d_in[5];
    const float* Wv_r  = (const float*)d_in[6];
    const float* Wv_i  = (const float*)d_in[7];
    const float* Wo_r  = (const float*)d_in[8];
    const float* Wo_i  = (const float*)d_in[9];
    const float* bo_r  = (const float*)d_in[10];
    const float* bo_i  = (const float*)d_in[11];
    const float* ln1_gr = (const float*)d_in[12];
    const float* ln1_gi = (const float*)d_in[13];
    const float* ln1_br = (const float*)d_in[14];
    const float* ln1_bi = (const float*)d_in[15];
    const float* ln2_gr = (const float*)d_in[16];
    const float* ln2_gi = (const float*)d_in[17];
    const float* ln2_br = (const float*)d_in[18];
    const float* ln2_bi = (const float*)d_in[19];
    const float* W1_r  = (const float*)d_in[20];
    const float* W1_i  = (const float*)d_in[21];
    const float* b1_r  = (const float*)d_in[22];
    const float* b1_i  = (const float*)d_in[23];
    const float* W2_r  = (const float*)d_in[24];
    const float* W2_i  = (const float*)d_in[25];
    const float* b2_r  = (const float*)d_in[26];
    const float* b2_i  = (const float*)d_in[27];
    const float* mod_b = (const float*)d_in[28];
    float* out = (float*)d_out;

    float *hr, *hi, *qr, *qi, *kr, *ki, *vr, *vi, *sb, *aor, *aoi, *ar, *ai, *fr, *fi;
    cudaGetSymbolAddress((void**)&hr,  g_hr);
    cudaGetSymbolAddress((void**)&hi,  g_hi);
    cudaGetSymbolAddress((void**)&qr,  g_qr);
    cudaGetSymbolAddress((void**)&qi,  g_qi);
    cudaGetSymbolAddress((void**)&kr,  g_kr);
    cudaGetSymbolAddress((void**)&ki,  g_ki);
    cudaGetSymbolAddress((void**)&vr,  g_vr);
    cudaGetSymbolAddress((void**)&vi,  g_vi);
    cudaGetSymbolAddress((void**)&sb,  g_s);
    cudaGetSymbolAddress((void**)&aor, g_aor);
    cudaGetSymbolAddress((void**)&aoi, g_aoi);
    cudaGetSymbolAddress((void**)&ar,  g_ar);
    cudaGetSymbolAddress((void**)&ai,  g_ai);
    cudaGetSymbolAddress((void**)&fr,  g_fr);
    cudaGetSymbolAddress((void**)&fi,  g_fi);

    cudaFuncSetAttribute(cmma_gemm,  cudaFuncAttributeMaxDynamicSharedMemorySize, SMEM_GEMM);
    cudaFuncSetAttribute(scores_mma, cudaFuncAttributeMaxDynamicSharedMemorySize, SMEM_SC);

    // 1. LN1
    cln_kernel<<<Mn, 256>>>(x_r, x_i, ln1_gr, ln1_gi, ln1_br, ln1_bi, hr, hi);

    // 2. QKV projections
    dim3 gproj(Dn/BNg, Mn/BMg);
    cmma_gemm<<<gproj, 256, SMEM_GEMM>>>(hr, hi, Wq_r, Wq_i, qr, qi, Mn, Dn, Dn, nullptr, nullptr, nullptr, nullptr);
    cmma_gemm<<<gproj, 256, SMEM_GEMM>>>(hr, hi, Wk_r, Wk_i, kr, ki, Mn, Dn, Dn, nullptr, nullptr, nullptr, nullptr);
    cmma_gemm<<<gproj, 256, SMEM_GEMM>>>(hr, hi, Wv_r, Wv_i, vr, vi, Mn, Dn, Dn, nullptr, nullptr, nullptr, nullptr);

    // 3. RoPE on Q and K
    rope_kernel<<<(Bn*Ln*Hn*32)/256, 256>>>(qr, qi);
    rope_kernel<<<(Bn*Ln*Hn*32)/256, 256>>>(kr, ki);

    // 4. scores + softmax + attn@V — all tensor-core now
    scores_mma<<<dim3(Ln/128, Ln/128, Bn*Hn), 256, SMEM_SC>>>(qr, qi, kr, ki, sb);
    softmax_kernel<<<Bn*Hn*Ln, 256>>>(sb);
    av_mma<<<dim3(1, Ln/128, Bn*Hn), 256>>>(sb, vr, vi, aor, aoi);

    // 5. out projection + bias + residual(x)
    cmma_gemm<<<gproj, 256, SMEM_GEMM>>>(aor, aoi, Wo_r, Wo_i, ar, ai, Mn, Dn, Dn, bo_r, bo_i, x_r, x_i);

    // 6. LN2
    cln_kernel<<<Mn, 256>>>(ar, ai, ln2_gr, ln2_gi, ln2_br, ln2_bi, hr, hi);

    // 7. FC1 + bias
    cmma_gemm<<<dim3(HIDn/BNg, Mn/BMg), 256, SMEM_GEMM>>>(hr, hi, W1_r, W1_i, fr, fi, Mn, HIDn, Dn, b1_r, b1_i, nullptr, nullptr);

    // 8. ModReLU
    modrelu_kernel<<<(Mn*(size_t)HIDn)/256, 256>>>(fr, fi, mod_b);

    // 9. FC2 + bias + residual(ar/ai) -> output
    cmma_gemm<<<gproj, 256, SMEM_GEMM>>>(fr, fi, W2_r, W2_i, out, out + (size_t)Mn*Dn, Mn, Dn, HIDn, b2_r, b2_i, ar, ai);
}